// round 1
// baseline (speedup 1.0000x reference)
#include <cuda_runtime.h>

#define NN 100000   // nodes
#define NE 500000   // edges
#define NH 4        // heads
#define HD 32       // hidden per head / output width
#define PROJ 128

// ---------------- device scratch (no allocations allowed) ----------------
__device__ __align__(16) float g_seg[NN * HD];   // per-node accumulated (wv @ Wout)
__device__ float g_cnt[NN];                      // per-node edge counts
__device__ float g_A[NH][3][3];                  // folded quadratic form (scaled by 1/sqrt(32))
__device__ float g_lin[NH][3];                   // folded linear term
__device__ float g_s0[NH];                       // folded constant term
__device__ __align__(16) float g_M[NH][3][HD];   // Wv_h @ Wout_h
__device__ __align__(16) float g_c[NH][HD];      // bv_h @ Wout_h
__device__ int g_is64;                           // edge_index dtype flag

// ---------------- kernel 1: zero scratch ----------------
__global__ void zero_kernel() {
    int i = blockIdx.x * blockDim.x + threadIdx.x;
    int stride = gridDim.x * blockDim.x;
    float4* s4 = reinterpret_cast<float4*>(g_seg);
    const int n4 = NN * HD / 4;
    for (int j = i; j < n4; j += stride) s4[j] = make_float4(0.f, 0.f, 0.f, 0.f);
    for (int j = i; j < NN; j += stride) g_cnt[j] = 0.f;
}

// ---------------- kernel 2: fold weights + detect int64 ----------------
__global__ void setup_kernel(const int* __restrict__ eraw,
                             const float* __restrict__ Wq, const float* __restrict__ bq,
                             const float* __restrict__ Wk, const float* __restrict__ bk,
                             const float* __restrict__ Wv, const float* __restrict__ bv,
                             const float* __restrict__ Wout) {
    const int t = threadIdx.x;
    const float inv = 0.17677669529663687f;  // 1/sqrt(32)

    if (t == 0) {
        // int64 edge_index: node ids < 1e5 -> every high 32-bit word is 0.
        int allz = 1;
        for (int i = 1; i < 64; i += 2) allz &= (eraw[i] == 0);
        g_is64 = allz;
    }

    // A_h[i][j] = sum_d Wq[i, h*32+d] * Wk[j, h*32+d]   (scaled)
    for (int idx = t; idx < NH * 9; idx += blockDim.x) {
        int h = idx / 9, i = (idx % 9) / 3, j = idx % 3;
        float s = 0.f;
        for (int d = 0; d < HD; d++)
            s += Wq[i * PROJ + h * HD + d] * Wk[j * PROJ + h * HD + d];
        g_A[h][i][j] = s * inv;
    }
    // lin_h[i] = sum_d (Wq[i,hd]*bk[hd] + Wk[i,hd]*bq[hd])   (scaled)
    for (int idx = t; idx < NH * 3; idx += blockDim.x) {
        int h = idx / 3, i = idx % 3;
        float s = 0.f;
        for (int d = 0; d < HD; d++)
            s += Wq[i * PROJ + h * HD + d] * bk[h * HD + d]
               + Wk[i * PROJ + h * HD + d] * bq[h * HD + d];
        g_lin[h][i] = s * inv;
    }
    // s0_h = bq_h . bk_h   (scaled)
    for (int idx = t; idx < NH; idx += blockDim.x) {
        float s = 0.f;
        for (int d = 0; d < HD; d++) s += bq[idx * HD + d] * bk[idx * HD + d];
        g_s0[idx] = s * inv;
    }
    // M_h[i][o] = sum_d Wv[i, h*32+d] * Wout[h*32+d, o]
    for (int idx = t; idx < NH * 3 * HD; idx += blockDim.x) {
        int h = idx / (3 * HD), i = (idx / HD) % 3, o = idx % HD;
        float s = 0.f;
        for (int d = 0; d < HD; d++)
            s += Wv[i * PROJ + h * HD + d] * Wout[(h * HD + d) * HD + o];
        g_M[h][i][o] = s;
    }
    // c_h[o] = sum_d bv[h*32+d] * Wout[h*32+d, o]
    for (int idx = t; idx < NH * HD; idx += blockDim.x) {
        int h = idx / HD, o = idx % HD;
        float s = 0.f;
        for (int d = 0; d < HD; d++)
            s += bv[h * HD + d] * Wout[(h * HD + d) * HD + o];
        g_c[h][o] = s;
    }
}

// ---------------- kernel 3: per-edge attention + scatter ----------------
__device__ __forceinline__ void red_add_v4(float* p, float4 v) {
    asm volatile("red.global.add.v4.f32 [%0], {%1,%2,%3,%4};"
                 :: "l"(p), "f"(v.x), "f"(v.y), "f"(v.z), "f"(v.w)
                 : "memory");
}

__global__ void __launch_bounds__(256) edge_kernel(const int* __restrict__ eraw,
                                                   const float* __restrict__ pos) {
    int e = blockIdx.x * blockDim.x + threadIdx.x;
    if (e >= NE) return;

    int row, col;
    if (g_is64) {
        const long long* p = reinterpret_cast<const long long*>(eraw);
        row = (int)__ldg(&p[e]);
        col = (int)__ldg(&p[NE + e]);
    } else {
        row = __ldg(&eraw[e]);
        col = __ldg(&eraw[NE + e]);
    }

    float r[3];
#pragma unroll
    for (int i = 0; i < 3; i++)
        r[i] = __ldg(&pos[row * 3 + i]) - __ldg(&pos[col * 3 + i]);

    // scores via folded quadratic form
    float s[NH];
    float mx = -1e30f;
#pragma unroll
    for (int h = 0; h < NH; h++) {
        float acc = g_s0[h];
#pragma unroll
        for (int i = 0; i < 3; i++) {
            float t = g_lin[h][i];
#pragma unroll
            for (int j = 0; j < 3; j++) t = fmaf(g_A[h][i][j], r[j], t);
            acc = fmaf(r[i], t, acc);
        }
        s[h] = acc;
        mx = fmaxf(mx, acc);
    }
    float a[NH], den = 0.f;
#pragma unroll
    for (int h = 0; h < NH; h++) { a[h] = __expf(s[h] - mx); den += a[h]; }
    float dinv = 1.0f / den;

    // y = sum_h attn_h * (rel @ M_h + c_h)   -> 32 floats
    float4 y[8];
#pragma unroll
    for (int k = 0; k < 8; k++) y[k] = make_float4(0.f, 0.f, 0.f, 0.f);

#pragma unroll
    for (int h = 0; h < NH; h++) {
        float ah = a[h] * dinv;
        float w0 = ah * r[0], w1 = ah * r[1], w2 = ah * r[2];
        const float4* m0 = reinterpret_cast<const float4*>(&g_M[h][0][0]);
        const float4* m1 = reinterpret_cast<const float4*>(&g_M[h][1][0]);
        const float4* m2 = reinterpret_cast<const float4*>(&g_M[h][2][0]);
        const float4* cc = reinterpret_cast<const float4*>(&g_c[h][0]);
#pragma unroll
        for (int k = 0; k < 8; k++) {
            float4 v0 = m0[k], v1 = m1[k], v2 = m2[k], vc = cc[k];
            y[k].x = fmaf(w0, v0.x, fmaf(w1, v1.x, fmaf(w2, v2.x, fmaf(ah, vc.x, y[k].x))));
            y[k].y = fmaf(w0, v0.y, fmaf(w1, v1.y, fmaf(w2, v2.y, fmaf(ah, vc.y, y[k].y))));
            y[k].z = fmaf(w0, v0.z, fmaf(w1, v1.z, fmaf(w2, v2.z, fmaf(ah, vc.z, y[k].z))));
            y[k].w = fmaf(w0, v0.w, fmaf(w1, v1.w, fmaf(w2, v2.w, fmaf(ah, vc.w, y[k].w))));
        }
    }

    float* base = &g_seg[(size_t)col * HD];
#pragma unroll
    for (int k = 0; k < 8; k++) red_add_v4(base + k * 4, y[k]);
    atomicAdd(&g_cnt[col], 1.0f);
}

// ---------------- kernel 4: per-node mean + bias + LayerNorm + SiLU ----------------
__global__ void __launch_bounds__(256) node_kernel(const float* __restrict__ bout,
                                                   const float* __restrict__ gamma,
                                                   const float* __restrict__ beta,
                                                   float* __restrict__ out) {
    int gt = blockIdx.x * blockDim.x + threadIdx.x;
    int n = gt >> 5;
    int lane = gt & 31;
    if (n >= NN) return;

    float cnt = g_cnt[n];
    float v = g_seg[n * HD + lane] / fmaxf(cnt, 1.f) + __ldg(&bout[lane]);

    float sum = v;
#pragma unroll
    for (int o = 16; o > 0; o >>= 1) sum += __shfl_xor_sync(0xffffffffu, sum, o);
    float mu = sum * (1.0f / 32.0f);
    float d = v - mu;
    float sq = d * d;
#pragma unroll
    for (int o = 16; o > 0; o >>= 1) sq += __shfl_xor_sync(0xffffffffu, sq, o);
    float var = sq * (1.0f / 32.0f);

    float x = d * rsqrtf(var + 1e-5f) * __ldg(&gamma[lane]) + __ldg(&beta[lane]);
    out[n * HD + lane] = x / (1.0f + __expf(-x));  // SiLU
}

// ---------------- launch ----------------
extern "C" void kernel_launch(void* const* d_in, const int* in_sizes, int n_in,
                              void* d_out, int out_size) {
    const float* pos   = (const float*)d_in[0];
    const int*   edge  = (const int*)d_in[1];
    const float* Wq    = (const float*)d_in[2];
    const float* bq    = (const float*)d_in[3];
    const float* Wk    = (const float*)d_in[4];
    const float* bk    = (const float*)d_in[5];
    const float* Wv    = (const float*)d_in[6];
    const float* bv    = (const float*)d_in[7];
    const float* Wout  = (const float*)d_in[8];
    const float* bout  = (const float*)d_in[9];
    const float* gamma = (const float*)d_in[10];
    const float* beta  = (const float*)d_in[11];
    float* out = (float*)d_out;

    zero_kernel<<<800, 256>>>();
    setup_kernel<<<1, 192>>>(edge, Wq, bq, Wk, bk, Wv, bv, Wout);
    edge_kernel<<<(NE + 255) / 256, 256>>>(edge, pos);
    node_kernel<<<(NN * HD + 255) / 256, 256>>>(bout, gamma, beta, out);
}

// round 2
// speedup vs baseline: 1.5305x; 1.5305x over previous
#include <cuda_runtime.h>

#define NN 100000   // nodes
#define NE 500000   // edges
#define NH 4        // heads
#define HD 32       // output width
#define PROJ 128
#define U16 16      // folded edge-feature width

// folded-parameter layout (floats)
#define A_OFF     0            // 4*3*3 = 36   quadratic form (pre-scaled 1/sqrt(32))
#define LIN_OFF   36           // 4*3  = 12
#define S0_OFF    48           // 4
#define B_OFF     52           // 16*32 = 512  (M_h rows + c_h rows interleaved per head)
#define BOUT_OFF  564          // 32
#define GAMMA_OFF 596          // 32
#define BETA_OFF  628          // 32
#define FOLD_SZ   660

// ---------------- device scratch (no allocations allowed) ----------------
__device__ __align__(16) float g_seg[NN * U16];  // per-node accumulated u-features
__device__ float g_fold[FOLD_SZ];                // staging for folded params
__device__ int   g_is64;                         // edge_index dtype flag
__constant__ float c_fold[FOLD_SZ];              // folded params (uniform-pipe loads)

// ---------------- kernel 1: zero scratch ----------------
__global__ void zero_kernel() {
    int i = blockIdx.x * blockDim.x + threadIdx.x;
    int stride = gridDim.x * blockDim.x;
    float4* s4 = reinterpret_cast<float4*>(g_seg);
    const int n4 = NN * U16 / 4;
    for (int j = i; j < n4; j += stride) s4[j] = make_float4(0.f, 0.f, 0.f, 0.f);
}

// ---------------- kernel 2: fold weights + detect edge dtype ----------------
__global__ void setup_kernel(const int* __restrict__ eraw,
                             const float* __restrict__ Wq, const float* __restrict__ bq,
                             const float* __restrict__ Wk, const float* __restrict__ bk,
                             const float* __restrict__ Wv, const float* __restrict__ bv,
                             const float* __restrict__ Wout, const float* __restrict__ bout,
                             const float* __restrict__ gamma, const float* __restrict__ beta) {
    const int t = threadIdx.x;
    const float inv = 0.17677669529663687f;  // 1/sqrt(32)

    if (t == 0) {
        // int64 edge_index: node ids < 1e5 -> every odd 32-bit word is 0.
        int allz = 1;
        for (int i = 1; i < 64; i += 2) allz &= (eraw[i] == 0);
        g_is64 = allz;
    }

    // A_h[i][j] = sum_d Wq[i, h*32+d] * Wk[j, h*32+d]   (scaled)
    for (int idx = t; idx < NH * 9; idx += blockDim.x) {
        int h = idx / 9, i = (idx % 9) / 3, j = idx % 3;
        float s = 0.f;
        for (int d = 0; d < HD; d++)
            s += Wq[i * PROJ + h * HD + d] * Wk[j * PROJ + h * HD + d];
        g_fold[A_OFF + idx] = s * inv;
    }
    // lin_h[i] = sum_d (Wq[i,hd]*bk[hd] + Wk[i,hd]*bq[hd])   (scaled)
    for (int idx = t; idx < NH * 3; idx += blockDim.x) {
        int h = idx / 3, i = idx % 3;
        float s = 0.f;
        for (int d = 0; d < HD; d++)
            s += Wq[i * PROJ + h * HD + d] * bk[h * HD + d]
               + Wk[i * PROJ + h * HD + d] * bq[h * HD + d];
        g_fold[LIN_OFF + idx] = s * inv;
    }
    // s0_h = bq_h . bk_h  (scaled)
    for (int idx = t; idx < NH; idx += blockDim.x) {
        float s = 0.f;
        for (int d = 0; d < HD; d++) s += bq[idx * HD + d] * bk[idx * HD + d];
        g_fold[S0_OFF + idx] = s * inv;
    }
    // B[(h*4+i)][o] = sum_d Wv[i, h*32+d] * Wout[h*32+d, o]   (i < 3)
    // B[(h*4+3)][o] = sum_d bv[h*32+d]    * Wout[h*32+d, o]
    for (int idx = t; idx < U16 * HD; idx += blockDim.x) {
        int j = idx / HD, o = idx % HD;
        int h = j / 4, i = j % 4;
        float s = 0.f;
        if (i < 3) {
            for (int d = 0; d < HD; d++)
                s += Wv[i * PROJ + h * HD + d] * Wout[(h * HD + d) * HD + o];
        } else {
            for (int d = 0; d < HD; d++)
                s += bv[h * HD + d] * Wout[(h * HD + d) * HD + o];
        }
        g_fold[B_OFF + idx] = s;
    }
    // raw epilogue params
    for (int idx = t; idx < HD; idx += blockDim.x) {
        g_fold[BOUT_OFF + idx]  = bout[idx];
        g_fold[GAMMA_OFF + idx] = gamma[idx];
        g_fold[BETA_OFF + idx]  = beta[idx];
    }
}

// ---------------- kernel 3: per-edge scores + 16-wide scatter ----------------
__device__ __forceinline__ void red_add_v4(float* p, float4 v) {
    asm volatile("red.global.add.v4.f32 [%0], {%1,%2,%3,%4};"
                 :: "l"(p), "f"(v.x), "f"(v.y), "f"(v.z), "f"(v.w)
                 : "memory");
}

__global__ void __launch_bounds__(256) edge_kernel(const int* __restrict__ eraw,
                                                   const float* __restrict__ pos) {
    int e = blockIdx.x * blockDim.x + threadIdx.x;
    if (e >= NE) return;

    int row, col;
    if (g_is64) {
        const long long* p = reinterpret_cast<const long long*>(eraw);
        row = (int)__ldg(&p[e]);
        col = (int)__ldg(&p[NE + e]);
    } else {
        row = __ldg(&eraw[e]);
        col = __ldg(&eraw[NE + e]);
    }

    float r[3];
#pragma unroll
    for (int i = 0; i < 3; i++)
        r[i] = __ldg(&pos[row * 3 + i]) - __ldg(&pos[col * 3 + i]);

    // scores via folded quadratic form (constant-memory params -> uniform pipe)
    float s[NH];
    float mx = -1e30f;
#pragma unroll
    for (int h = 0; h < NH; h++) {
        float acc = c_fold[S0_OFF + h];
#pragma unroll
        for (int i = 0; i < 3; i++) {
            float t = c_fold[LIN_OFF + h * 3 + i];
#pragma unroll
            for (int j = 0; j < 3; j++)
                t = fmaf(c_fold[A_OFF + h * 9 + i * 3 + j], r[j], t);
            acc = fmaf(r[i], t, acc);
        }
        s[h] = acc;
        mx = fmaxf(mx, acc);
    }
    float a[NH], den = 0.f;
#pragma unroll
    for (int h = 0; h < NH; h++) { a[h] = __expf(s[h] - mx); den += a[h]; }
    float dinv = 1.0f / den;

    // u[h*4+{0,1,2}] = a_h * r ; u[h*4+3] = a_h  (softmax sums to 1 => implicit count)
    float* base = &g_seg[(size_t)col * U16];
#pragma unroll
    for (int h = 0; h < NH; h++) {
        float ah = a[h] * dinv;
        red_add_v4(base + h * 4, make_float4(ah * r[0], ah * r[1], ah * r[2], ah));
    }
}

// ---------------- kernel 4: per-node u@B + mean + LayerNorm + SiLU ----------------
__global__ void __launch_bounds__(128) node_kernel(float* __restrict__ out) {
    int n = blockIdx.x * blockDim.x + threadIdx.x;
    if (n >= NN) return;

    float s[U16];
    const float4* sp = reinterpret_cast<const float4*>(&g_seg[(size_t)n * U16]);
#pragma unroll
    for (int k = 0; k < 4; k++) {
        float4 v = sp[k];
        s[k * 4 + 0] = v.x; s[k * 4 + 1] = v.y; s[k * 4 + 2] = v.z; s[k * 4 + 3] = v.w;
    }

    float cnt = s[3] + s[7] + s[11] + s[15];      // = number of incoming edges
    float rinv = 1.0f / fmaxf(cnt, 1.0f);

    float y[HD];
    float sum = 0.f;
#pragma unroll
    for (int o = 0; o < HD; o++) {
        float acc = 0.f;
#pragma unroll
        for (int j = 0; j < U16; j++)
            acc = fmaf(s[j], c_fold[B_OFF + j * HD + o], acc);
        y[o] = acc * rinv + c_fold[BOUT_OFF + o];
        sum += y[o];
    }
    float mu = sum * (1.0f / 32.0f);
    float sq = 0.f;
#pragma unroll
    for (int o = 0; o < HD; o++) { float d = y[o] - mu; sq += d * d; }
    float sfac = rsqrtf(sq * (1.0f / 32.0f) + 1e-5f);

    float4* op = reinterpret_cast<float4*>(&out[(size_t)n * HD]);
#pragma unroll
    for (int k = 0; k < 8; k++) {
        float4 v;
        float* vp = &v.x;
#pragma unroll
        for (int c = 0; c < 4; c++) {
            int o = k * 4 + c;
            float x = (y[o] - mu) * sfac * c_fold[GAMMA_OFF + o] + c_fold[BETA_OFF + o];
            vp[c] = x / (1.0f + __expf(-x));      // SiLU
        }
        op[k] = v;
    }
}

// ---------------- launch ----------------
extern "C" void kernel_launch(void* const* d_in, const int* in_sizes, int n_in,
                              void* d_out, int out_size) {
    const float* pos   = (const float*)d_in[0];
    const int*   edge  = (const int*)d_in[1];
    const float* Wq    = (const float*)d_in[2];
    const float* bq    = (const float*)d_in[3];
    const float* Wk    = (const float*)d_in[4];
    const float* bk    = (const float*)d_in[5];
    const float* Wv    = (const float*)d_in[6];
    const float* bv    = (const float*)d_in[7];
    const float* Wout  = (const float*)d_in[8];
    const float* bout  = (const float*)d_in[9];
    const float* gamma = (const float*)d_in[10];
    const float* beta  = (const float*)d_in[11];
    float* out = (float*)d_out;

    zero_kernel<<<400, 256>>>();
    setup_kernel<<<1, 192>>>(edge, Wq, bq, Wk, bk, Wv, bv, Wout, bout, gamma, beta);

    // stage folded params into constant memory (capturable D2D copy)
    void* src = nullptr;
    cudaGetSymbolAddress(&src, g_fold);
    cudaMemcpyToSymbolAsync(c_fold, src, FOLD_SZ * sizeof(float), 0,
                            cudaMemcpyDeviceToDevice, 0);

    edge_kernel<<<(NE + 255) / 256, 256>>>(edge, pos);
    node_kernel<<<(NN + 127) / 128, 128>>>(out);
}

// round 3
// speedup vs baseline: 1.8479x; 1.2074x over previous
#include <cuda_runtime.h>

#define NN 100000   // nodes
#define NE 500000   // edges
#define NH 4        // heads
#define HD 32       // output width
#define PROJ 128
#define U16 16      // folded edge-feature width

// folded-parameter layout inside g_fold (floats)
#define A_OFF     0            // 4*3*3 = 36  quadratic form (pre-scaled 1/sqrt(32))
#define LIN_OFF   36           // 4*3  = 12
#define S0_OFF    48           // 4
#define SCORE_SZ  52
#define B_OFF     52           // 16*32 = 512
#define BOUT_OFF  564          // 32
#define GAMMA_OFF 596          // 32
#define BETA_OFF  628          // 32
#define FOLD_SZ   660

// ---------------- device scratch (no allocations allowed) ----------------
__device__ __align__(16) float g_seg[NN * U16];  // per-node accumulated u-features
__device__ __align__(16) float g_fold[FOLD_SZ];  // folded params
__device__ int   g_is64;                         // edge_index dtype flag

// ---------------- kernel 1: zero scratch ----------------
__global__ void zero_kernel() {
    int i = blockIdx.x * blockDim.x + threadIdx.x;
    int stride = gridDim.x * blockDim.x;
    float4* s4 = reinterpret_cast<float4*>(g_seg);
    const int n4 = NN * U16 / 4;
    for (int j = i; j < n4; j += stride) s4[j] = make_float4(0.f, 0.f, 0.f, 0.f);
}

// ---------------- kernel 2: fold weights + detect edge dtype ----------------
__global__ void setup_kernel(const int* __restrict__ eraw,
                             const float* __restrict__ Wq, const float* __restrict__ bq,
                             const float* __restrict__ Wk, const float* __restrict__ bk,
                             const float* __restrict__ Wv, const float* __restrict__ bv,
                             const float* __restrict__ Wout, const float* __restrict__ bout,
                             const float* __restrict__ gamma, const float* __restrict__ beta) {
    const int t = threadIdx.x;
    const float inv = 0.17677669529663687f;  // 1/sqrt(32)

    if (t == 0) {
        // int64 edge_index: node ids < 1e5 -> every odd 32-bit word is 0.
        int allz = 1;
        for (int i = 1; i < 64; i += 2) allz &= (eraw[i] == 0);
        g_is64 = allz;
    }

    // A_h[i][j] = sum_d Wq[i, h*32+d] * Wk[j, h*32+d]   (scaled)
    for (int idx = t; idx < NH * 9; idx += blockDim.x) {
        int h = idx / 9, i = (idx % 9) / 3, j = idx % 3;
        float s = 0.f;
        for (int d = 0; d < HD; d++)
            s += Wq[i * PROJ + h * HD + d] * Wk[j * PROJ + h * HD + d];
        g_fold[A_OFF + idx] = s * inv;
    }
    // lin_h[i] = sum_d (Wq[i,hd]*bk[hd] + Wk[i,hd]*bq[hd])   (scaled)
    for (int idx = t; idx < NH * 3; idx += blockDim.x) {
        int h = idx / 3, i = idx % 3;
        float s = 0.f;
        for (int d = 0; d < HD; d++)
            s += Wq[i * PROJ + h * HD + d] * bk[h * HD + d]
               + Wk[i * PROJ + h * HD + d] * bq[h * HD + d];
        g_fold[LIN_OFF + idx] = s * inv;
    }
    // s0_h = bq_h . bk_h  (scaled)
    for (int idx = t; idx < NH; idx += blockDim.x) {
        float s = 0.f;
        for (int d = 0; d < HD; d++) s += bq[idx * HD + d] * bk[idx * HD + d];
        g_fold[S0_OFF + idx] = s * inv;
    }
    // B[(h*4+i)][o] = sum_d Wv[i, h*32+d] * Wout[h*32+d, o]   (i < 3)
    // B[(h*4+3)][o] = sum_d bv[h*32+d]    * Wout[h*32+d, o]
    for (int idx = t; idx < U16 * HD; idx += blockDim.x) {
        int j = idx / HD, o = idx % HD;
        int h = j / 4, i = j % 4;
        float s = 0.f;
        if (i < 3) {
            for (int d = 0; d < HD; d++)
                s += Wv[i * PROJ + h * HD + d] * Wout[(h * HD + d) * HD + o];
        } else {
            for (int d = 0; d < HD; d++)
                s += bv[h * HD + d] * Wout[(h * HD + d) * HD + o];
        }
        g_fold[B_OFF + idx] = s;
    }
    // raw epilogue params
    for (int idx = t; idx < HD; idx += blockDim.x) {
        g_fold[BOUT_OFF + idx]  = bout[idx];
        g_fold[GAMMA_OFF + idx] = gamma[idx];
        g_fold[BETA_OFF + idx]  = beta[idx];
    }
}

// ---------------- kernel 3: per-edge scores + 16-wide scatter ----------------
__device__ __forceinline__ void red_add_v4(float* p, float4 v) {
    asm volatile("red.global.add.v4.f32 [%0], {%1,%2,%3,%4};"
                 :: "l"(p), "f"(v.x), "f"(v.y), "f"(v.z), "f"(v.w)
                 : "memory");
}

__global__ void __launch_bounds__(256) edge_kernel(const int* __restrict__ eraw,
                                                   const float* __restrict__ pos) {
    __shared__ float sp[SCORE_SZ];   // A (36) | lin (12) | s0 (4)
    if (threadIdx.x < SCORE_SZ) sp[threadIdx.x] = g_fold[threadIdx.x];
    __syncthreads();

    int e = blockIdx.x * blockDim.x + threadIdx.x;
    if (e >= NE) return;

    int row, col;
    if (g_is64) {
        const long long* p = reinterpret_cast<const long long*>(eraw);
        row = (int)__ldg(&p[e]);
        col = (int)__ldg(&p[NE + e]);
    } else {
        row = __ldg(&eraw[e]);
        col = __ldg(&eraw[NE + e]);
    }

    float r[3];
#pragma unroll
    for (int i = 0; i < 3; i++)
        r[i] = __ldg(&pos[row * 3 + i]) - __ldg(&pos[col * 3 + i]);

    // scores via folded quadratic form (smem broadcast loads)
    float s[NH];
    float mx = -1e30f;
#pragma unroll
    for (int h = 0; h < NH; h++) {
        float acc = sp[S0_OFF + h];
#pragma unroll
        for (int i = 0; i < 3; i++) {
            float t = sp[LIN_OFF + h * 3 + i];
#pragma unroll
            for (int j = 0; j < 3; j++)
                t = fmaf(sp[A_OFF + h * 9 + i * 3 + j], r[j], t);
            acc = fmaf(r[i], t, acc);
        }
        s[h] = acc;
        mx = fmaxf(mx, acc);
    }
    float a[NH], den = 0.f;
#pragma unroll
    for (int h = 0; h < NH; h++) { a[h] = __expf(s[h] - mx); den += a[h]; }
    float dinv = 1.0f / den;

    // u[h*4+{0,1,2}] = a_h * r ; u[h*4+3] = a_h  (softmax sums to 1 => implicit count)
    float* base = &g_seg[(size_t)col * U16];
#pragma unroll
    for (int h = 0; h < NH; h++) {
        float ah = a[h] * dinv;
        red_add_v4(base + h * 4, make_float4(ah * r[0], ah * r[1], ah * r[2], ah));
    }
}

// ---------------- kernel 4: per-node u@B + mean + LayerNorm + SiLU ----------------
__global__ void __launch_bounds__(256) node_kernel(float* __restrict__ out) {
    __shared__ __align__(16) float sB[U16 * HD];   // 512 floats
    __shared__ __align__(16) float sEpi[3 * HD];   // bout | gamma | beta

    for (int i = threadIdx.x; i < U16 * HD; i += 256) sB[i] = g_fold[B_OFF + i];
    for (int i = threadIdx.x; i < 3 * HD; i += 256)  sEpi[i] = g_fold[BOUT_OFF + i];
    __syncthreads();

    int n = blockIdx.x * blockDim.x + threadIdx.x;
    if (n >= NN) return;

    float s[U16];
    const float4* spv = reinterpret_cast<const float4*>(&g_seg[(size_t)n * U16]);
#pragma unroll
    for (int k = 0; k < 4; k++) {
        float4 v = spv[k];
        s[k * 4 + 0] = v.x; s[k * 4 + 1] = v.y; s[k * 4 + 2] = v.z; s[k * 4 + 3] = v.w;
    }

    float cnt = s[3] + s[7] + s[11] + s[15];      // number of incoming edges
    float rinv = 1.0f / fmaxf(cnt, 1.0f);

    // y = s @ B  with o-inner so B reads are float4 (LDS.128 broadcast)
    float y[HD];
#pragma unroll
    for (int o = 0; o < HD; o++) y[o] = 0.f;
#pragma unroll
    for (int j = 0; j < U16; j++) {
        float sj = s[j];
        const float4* brow = reinterpret_cast<const float4*>(&sB[j * HD]);
#pragma unroll
        for (int k = 0; k < 8; k++) {
            float4 b = brow[k];
            y[k * 4 + 0] = fmaf(sj, b.x, y[k * 4 + 0]);
            y[k * 4 + 1] = fmaf(sj, b.y, y[k * 4 + 1]);
            y[k * 4 + 2] = fmaf(sj, b.z, y[k * 4 + 2]);
            y[k * 4 + 3] = fmaf(sj, b.w, y[k * 4 + 3]);
        }
    }

    float sum = 0.f;
#pragma unroll
    for (int o = 0; o < HD; o++) {
        y[o] = fmaf(y[o], rinv, sEpi[o]);          // mean + bout
        sum += y[o];
    }
    float mu = sum * (1.0f / 32.0f);
    float sq = 0.f;
#pragma unroll
    for (int o = 0; o < HD; o++) { float d = y[o] - mu; sq = fmaf(d, d, sq); }
    float sfac = rsqrtf(sq * (1.0f / 32.0f) + 1e-5f);

    float4* op = reinterpret_cast<float4*>(&out[(size_t)n * HD]);
#pragma unroll
    for (int k = 0; k < 8; k++) {
        float4 v;
        float* vp = &v.x;
#pragma unroll
        for (int c = 0; c < 4; c++) {
            int o = k * 4 + c;
            float x = (y[o] - mu) * sfac * sEpi[HD + o] + sEpi[2 * HD + o];
            vp[c] = x / (1.0f + __expf(-x));       // SiLU
        }
        op[k] = v;
    }
}

// ---------------- launch ----------------
extern "C" void kernel_launch(void* const* d_in, const int* in_sizes, int n_in,
                              void* d_out, int out_size) {
    const float* pos   = (const float*)d_in[0];
    const int*   edge  = (const int*)d_in[1];
    const float* Wq    = (const float*)d_in[2];
    const float* bq    = (const float*)d_in[3];
    const float* Wk    = (const float*)d_in[4];
    const float* bk    = (const float*)d_in[5];
    const float* Wv    = (const float*)d_in[6];
    const float* bv    = (const float*)d_in[7];
    const float* Wout  = (const float*)d_in[8];
    const float* bout  = (const float*)d_in[9];
    const float* gamma = (const float*)d_in[10];
    const float* beta  = (const float*)d_in[11];
    float* out = (float*)d_out;

    zero_kernel<<<592, 256>>>();
    setup_kernel<<<1, 256>>>(edge, Wq, bq, Wk, bk, Wv, bv, Wout, bout, gamma, beta);
    edge_kernel<<<(NE + 255) / 256, 256>>>(edge, pos);
    node_kernel<<<(NN + 255) / 256, 256>>>(out);
}

// round 4
// speedup vs baseline: 1.9419x; 1.0508x over previous
#include <cuda_runtime.h>

#define NN 100000   // nodes
#define NE 500000   // edges
#define NH 4        // heads
#define HD 32       // output width
#define PROJ 128
#define U16 16      // folded edge-feature width

// folded-parameter layout inside g_fold (floats)
#define A_OFF     0            // 4*3*3 = 36  quadratic form (pre-scaled 1/sqrt(32))
#define LIN_OFF   36           // 4*3  = 12
#define S0_OFF    48           // 4
#define SCORE_SZ  52
#define B_OFF     52           // 16*32 = 512
#define BOUT_OFF  564          // 32
#define GAMMA_OFF 596          // 32
#define BETA_OFF  628          // 32
#define FOLD_SZ   660

// ---------------- device scratch (no allocations allowed) ----------------
__device__ __align__(16) float g_seg[NN * U16];  // per-node accumulated u-features
__device__ __align__(16) float4 g_pos4[NN];      // padded positions for 1-LDG gathers
__device__ __align__(16) float g_fold[FOLD_SZ];  // folded params
__device__ int   g_is64;                         // edge_index dtype flag

// ---------------- kernel 1: zero scratch + pack positions ----------------
__global__ void zero_pack_kernel(const float* __restrict__ pos) {
    int i = blockIdx.x * blockDim.x + threadIdx.x;
    int stride = gridDim.x * blockDim.x;
    float4* s4 = reinterpret_cast<float4*>(g_seg);
    const int n4 = NN * U16 / 4;
    for (int j = i; j < n4; j += stride) s4[j] = make_float4(0.f, 0.f, 0.f, 0.f);
    for (int j = i; j < NN; j += stride)
        g_pos4[j] = make_float4(__ldg(&pos[j * 3 + 0]),
                                __ldg(&pos[j * 3 + 1]),
                                __ldg(&pos[j * 3 + 2]), 0.f);
}

// ---------------- kernel 2: fold weights + detect edge dtype ----------------
__global__ void setup_kernel(const int* __restrict__ eraw,
                             const float* __restrict__ Wq, const float* __restrict__ bq,
                             const float* __restrict__ Wk, const float* __restrict__ bk,
                             const float* __restrict__ Wv, const float* __restrict__ bv,
                             const float* __restrict__ Wout, const float* __restrict__ bout,
                             const float* __restrict__ gamma, const float* __restrict__ beta) {
    const int t = threadIdx.x;
    const float inv = 0.17677669529663687f;  // 1/sqrt(32)

    if (t == 0) {
        // int64 edge_index: node ids < 1e5 -> every odd 32-bit word is 0.
        int allz = 1;
        for (int i = 1; i < 64; i += 2) allz &= (eraw[i] == 0);
        g_is64 = allz;
    }

    // A_h[i][j] = sum_d Wq[i, h*32+d] * Wk[j, h*32+d]   (scaled)
    for (int idx = t; idx < NH * 9; idx += blockDim.x) {
        int h = idx / 9, i = (idx % 9) / 3, j = idx % 3;
        float s = 0.f;
        for (int d = 0; d < HD; d++)
            s += Wq[i * PROJ + h * HD + d] * Wk[j * PROJ + h * HD + d];
        g_fold[A_OFF + idx] = s * inv;
    }
    // lin_h[i] = sum_d (Wq[i,hd]*bk[hd] + Wk[i,hd]*bq[hd])   (scaled)
    for (int idx = t; idx < NH * 3; idx += blockDim.x) {
        int h = idx / 3, i = idx % 3;
        float s = 0.f;
        for (int d = 0; d < HD; d++)
            s += Wq[i * PROJ + h * HD + d] * bk[h * HD + d]
               + Wk[i * PROJ + h * HD + d] * bq[h * HD + d];
        g_fold[LIN_OFF + idx] = s * inv;
    }
    // s0_h = bq_h . bk_h  (scaled)
    for (int idx = t; idx < NH; idx += blockDim.x) {
        float s = 0.f;
        for (int d = 0; d < HD; d++) s += bq[idx * HD + d] * bk[idx * HD + d];
        g_fold[S0_OFF + idx] = s * inv;
    }
    // B[(h*4+i)][o] = sum_d Wv[i, h*32+d] * Wout[h*32+d, o]   (i < 3)
    // B[(h*4+3)][o] = sum_d bv[h*32+d]    * Wout[h*32+d, o]
    for (int idx = t; idx < U16 * HD; idx += blockDim.x) {
        int j = idx / HD, o = idx % HD;
        int h = j / 4, i = j % 4;
        float s = 0.f;
        if (i < 3) {
            for (int d = 0; d < HD; d++)
                s += Wv[i * PROJ + h * HD + d] * Wout[(h * HD + d) * HD + o];
        } else {
            for (int d = 0; d < HD; d++)
                s += bv[h * HD + d] * Wout[(h * HD + d) * HD + o];
        }
        g_fold[B_OFF + idx] = s;
    }
    // raw epilogue params
    for (int idx = t; idx < HD; idx += blockDim.x) {
        g_fold[BOUT_OFF + idx]  = bout[idx];
        g_fold[GAMMA_OFF + idx] = gamma[idx];
        g_fold[BETA_OFF + idx]  = beta[idx];
    }
}

// ---------------- kernel 3: per-edge scores + 16-wide scatter ----------------
__device__ __forceinline__ void red_add_v4(float* p, float4 v) {
    asm volatile("red.global.add.v4.f32 [%0], {%1,%2,%3,%4};"
                 :: "l"(p), "f"(v.x), "f"(v.y), "f"(v.z), "f"(v.w)
                 : "memory");
}

__global__ void __launch_bounds__(256) edge_kernel(const int* __restrict__ eraw) {
    __shared__ float sp[SCORE_SZ];   // A (36) | lin (12) | s0 (4)
    if (threadIdx.x < SCORE_SZ) sp[threadIdx.x] = g_fold[threadIdx.x];
    __syncthreads();

    int e = blockIdx.x * blockDim.x + threadIdx.x;
    if (e >= NE) return;

    int row, col;
    if (g_is64) {
        const long long* p = reinterpret_cast<const long long*>(eraw);
        row = (int)__ldg(&p[e]);
        col = (int)__ldg(&p[NE + e]);
    } else {
        row = __ldg(&eraw[e]);
        col = __ldg(&eraw[NE + e]);
    }

    float4 pr = g_pos4[row];
    float4 pc = g_pos4[col];
    float r[3] = { pr.x - pc.x, pr.y - pc.y, pr.z - pc.z };

    // scores via folded quadratic form (smem broadcast loads)
    float s[NH];
    float mx = -1e30f;
#pragma unroll
    for (int h = 0; h < NH; h++) {
        float acc = sp[S0_OFF + h];
#pragma unroll
        for (int i = 0; i < 3; i++) {
            float t = sp[LIN_OFF + h * 3 + i];
#pragma unroll
            for (int j = 0; j < 3; j++)
                t = fmaf(sp[A_OFF + h * 9 + i * 3 + j], r[j], t);
            acc = fmaf(r[i], t, acc);
        }
        s[h] = acc;
        mx = fmaxf(mx, acc);
    }
    float a[NH], den = 0.f;
#pragma unroll
    for (int h = 0; h < NH; h++) { a[h] = __expf(s[h] - mx); den += a[h]; }
    float dinv = 1.0f / den;

    // u[h*4+{0,1,2}] = a_h * r ; u[h*4+3] = a_h  (softmax sums to 1 => implicit count)
    float* base = &g_seg[(size_t)col * U16];
#pragma unroll
    for (int h = 0; h < NH; h++) {
        float ah = a[h] * dinv;
        red_add_v4(base + h * 4, make_float4(ah * r[0], ah * r[1], ah * r[2], ah));
    }
}

// ---------------- kernel 4: per-node u@B + mean + LN + SiLU (4 threads/node) ----------------
__global__ void __launch_bounds__(256) node_kernel(float* __restrict__ out) {
    __shared__ __align__(16) float sB[U16 * HD];   // 512 floats
    __shared__ __align__(16) float sEpi[3 * HD];   // bout | gamma | beta

    for (int i = threadIdx.x; i < U16 * HD; i += 256) sB[i] = g_fold[B_OFF + i];
    for (int i = threadIdx.x; i < 3 * HD; i += 256)  sEpi[i] = g_fold[BOUT_OFF + i];
    __syncthreads();

    int gt  = blockIdx.x * blockDim.x + threadIdx.x;
    int n   = gt >> 2;           // node
    int sub = gt & 3;            // which 8-output slice
    if (n >= NN) return;
    unsigned mask = __activemask();

    // all 4 threads of the quad load the full 16-wide feature (L1 broadcast)
    float s[U16];
    const float4* spv = reinterpret_cast<const float4*>(&g_seg[(size_t)n * U16]);
#pragma unroll
    for (int k = 0; k < 4; k++) {
        float4 v = spv[k];
        s[k * 4 + 0] = v.x; s[k * 4 + 1] = v.y; s[k * 4 + 2] = v.z; s[k * 4 + 3] = v.w;
    }

    float cnt  = s[3] + s[7] + s[11] + s[15];     // number of incoming edges
    float rinv = 1.0f / fmaxf(cnt, 1.0f);

    // y[sub*8 .. sub*8+7] = s @ B slice ; B slice reads are LDS.128, conflict-free
    const int o0 = sub * 8;
    float y[8];
#pragma unroll
    for (int c = 0; c < 8; c++) y[c] = 0.f;
#pragma unroll
    for (int j = 0; j < U16; j++) {
        float sj = s[j];
        const float4* brow = reinterpret_cast<const float4*>(&sB[j * HD + o0]);
        float4 b0 = brow[0], b1 = brow[1];
        y[0] = fmaf(sj, b0.x, y[0]); y[1] = fmaf(sj, b0.y, y[1]);
        y[2] = fmaf(sj, b0.z, y[2]); y[3] = fmaf(sj, b0.w, y[3]);
        y[4] = fmaf(sj, b1.x, y[4]); y[5] = fmaf(sj, b1.y, y[5]);
        y[6] = fmaf(sj, b1.z, y[6]); y[7] = fmaf(sj, b1.w, y[7]);
    }

    float sum = 0.f;
#pragma unroll
    for (int c = 0; c < 8; c++) {
        y[c] = fmaf(y[c], rinv, sEpi[o0 + c]);     // mean + bout
        sum += y[c];
    }
    // quad reduction for mean
    sum += __shfl_xor_sync(mask, sum, 1);
    sum += __shfl_xor_sync(mask, sum, 2);
    float mu = sum * (1.0f / 32.0f);

    float sq = 0.f;
#pragma unroll
    for (int c = 0; c < 8; c++) { float d = y[c] - mu; sq = fmaf(d, d, sq); }
    sq += __shfl_xor_sync(mask, sq, 1);
    sq += __shfl_xor_sync(mask, sq, 2);
    float sfac = rsqrtf(sq * (1.0f / 32.0f) + 1e-5f);

    float4* op = reinterpret_cast<float4*>(&out[(size_t)n * HD + o0]);
#pragma unroll
    for (int k = 0; k < 2; k++) {
        float4 v;
        float* vp = &v.x;
#pragma unroll
        for (int c = 0; c < 4; c++) {
            int o = o0 + k * 4 + c;
            float x = (y[k * 4 + c] - mu) * sfac * sEpi[HD + o] + sEpi[2 * HD + o];
            vp[c] = x / (1.0f + __expf(-x));       // SiLU
        }
        op[k] = v;
    }
}

// ---------------- launch ----------------
extern "C" void kernel_launch(void* const* d_in, const int* in_sizes, int n_in,
                              void* d_out, int out_size) {
    const float* pos   = (const float*)d_in[0];
    const int*   edge  = (const int*)d_in[1];
    const float* Wq    = (const float*)d_in[2];
    const float* bq    = (const float*)d_in[3];
    const float* Wk    = (const float*)d_in[4];
    const float* bk    = (const float*)d_in[5];
    const float* Wv    = (const float*)d_in[6];
    const float* bv    = (const float*)d_in[7];
    const float* Wout  = (const float*)d_in[8];
    const float* bout  = (const float*)d_in[9];
    const float* gamma = (const float*)d_in[10];
    const float* beta  = (const float*)d_in[11];
    float* out = (float*)d_out;

    zero_pack_kernel<<<592, 256>>>(pos);
    setup_kernel<<<1, 256>>>(edge, Wq, bq, Wk, bk, Wv, bv, Wout, bout, gamma, beta);
    edge_kernel<<<(NE + 255) / 256, 256>>>(edge);
    node_kernel<<<(NN * 4 + 255) / 256, 256>>>(out);
}

// round 5
// speedup vs baseline: 2.0459x; 1.0536x over previous
#include <cuda_runtime.h>

#define NN 100000   // nodes
#define NE 500000   // edges
#define NH 4        // heads
#define HD 32       // output width
#define PROJ 128
#define U16 16      // folded edge-feature width

// folded-parameter layout inside g_fold (floats)
#define A_OFF     0            // 4*3*3 = 36  quadratic form (pre-scaled 1/sqrt(32))
#define LIN_OFF   36           // 4*3  = 12
#define S0_OFF    48           // 4
#define SCORE_SZ  52
#define B_OFF     52           // 16*32 = 512
#define BOUT_OFF  564          // 32
#define GAMMA_OFF 596          // 32
#define BETA_OFF  628          // 32
#define FOLD_SZ   660

// ---------------- device scratch (no allocations allowed) ----------------
// g_seg starts zeroed (static init) and is re-zeroed by node_kernel every
// launch after it consumes the values, so each edge_kernel sees zeros.
__device__ __align__(16) float g_seg[NN * U16];
__device__ __align__(16) float4 g_pos4[NN];      // padded positions for 1-LDG gathers
__device__ __align__(16) float g_fold[FOLD_SZ];  // folded params
__device__ int   g_is64;                         // edge_index dtype flag

// ---------------- kernel 1: pack positions + (block 0) fold weights ----------------
__global__ void pack_setup_kernel(const float* __restrict__ pos,
                                  const int* __restrict__ eraw,
                                  const float* __restrict__ Wq, const float* __restrict__ bq,
                                  const float* __restrict__ Wk, const float* __restrict__ bk,
                                  const float* __restrict__ Wv, const float* __restrict__ bv,
                                  const float* __restrict__ Wout, const float* __restrict__ bout,
                                  const float* __restrict__ gamma, const float* __restrict__ beta) {
    int i = blockIdx.x * blockDim.x + threadIdx.x;
    int stride = gridDim.x * blockDim.x;
    for (int j = i; j < NN; j += stride)
        g_pos4[j] = make_float4(__ldg(&pos[j * 3 + 0]),
                                __ldg(&pos[j * 3 + 1]),
                                __ldg(&pos[j * 3 + 2]), 0.f);

    if (blockIdx.x != 0) return;
    const int t = threadIdx.x;
    const float inv = 0.17677669529663687f;  // 1/sqrt(32)

    if (t == 0) {
        // int64 edge_index: node ids < 1e5 -> every odd 32-bit word is 0.
        int allz = 1;
        for (int k = 1; k < 64; k += 2) allz &= (eraw[k] == 0);
        g_is64 = allz;
    }
    // A_h[i][j] = sum_d Wq[i, h*32+d] * Wk[j, h*32+d]   (scaled)
    for (int idx = t; idx < NH * 9; idx += blockDim.x) {
        int h = idx / 9, ii = (idx % 9) / 3, jj = idx % 3;
        float s = 0.f;
        for (int d = 0; d < HD; d++)
            s += Wq[ii * PROJ + h * HD + d] * Wk[jj * PROJ + h * HD + d];
        g_fold[A_OFF + idx] = s * inv;
    }
    // lin_h[i] = sum_d (Wq[i,hd]*bk[hd] + Wk[i,hd]*bq[hd])   (scaled)
    for (int idx = t; idx < NH * 3; idx += blockDim.x) {
        int h = idx / 3, ii = idx % 3;
        float s = 0.f;
        for (int d = 0; d < HD; d++)
            s += Wq[ii * PROJ + h * HD + d] * bk[h * HD + d]
               + Wk[ii * PROJ + h * HD + d] * bq[h * HD + d];
        g_fold[LIN_OFF + idx] = s * inv;
    }
    // s0_h = bq_h . bk_h  (scaled)
    for (int idx = t; idx < NH; idx += blockDim.x) {
        float s = 0.f;
        for (int d = 0; d < HD; d++) s += bq[idx * HD + d] * bk[idx * HD + d];
        g_fold[S0_OFF + idx] = s * inv;
    }
    // B[(h*4+i)][o] = sum_d Wv[i, h*32+d] * Wout[h*32+d, o]   (i < 3)
    // B[(h*4+3)][o] = sum_d bv[h*32+d]    * Wout[h*32+d, o]
    for (int idx = t; idx < U16 * HD; idx += blockDim.x) {
        int j = idx / HD, o = idx % HD;
        int h = j / 4, ii = j % 4;
        float s = 0.f;
        if (ii < 3) {
            for (int d = 0; d < HD; d++)
                s += Wv[ii * PROJ + h * HD + d] * Wout[(h * HD + d) * HD + o];
        } else {
            for (int d = 0; d < HD; d++)
                s += bv[h * HD + d] * Wout[(h * HD + d) * HD + o];
        }
        g_fold[B_OFF + idx] = s;
    }
    // raw epilogue params
    for (int idx = t; idx < HD; idx += blockDim.x) {
        g_fold[BOUT_OFF + idx]  = bout[idx];
        g_fold[GAMMA_OFF + idx] = gamma[idx];
        g_fold[BETA_OFF + idx]  = beta[idx];
    }
}

// ---------------- kernel 2: per-edge scores + 16-wide scatter (2 edges/thread) ----------------
__device__ __forceinline__ void red_add_v4(float* p, float4 v) {
    asm volatile("red.global.add.v4.f32 [%0], {%1,%2,%3,%4};"
                 :: "l"(p), "f"(v.x), "f"(v.y), "f"(v.z), "f"(v.w)
                 : "memory");
}

__device__ __forceinline__ void edge_compute(const float* sp, int col, float4 pr, float4 pc) {
    float r[3] = { pr.x - pc.x, pr.y - pc.y, pr.z - pc.z };
    float s[NH];
    float mx = -1e30f;
#pragma unroll
    for (int h = 0; h < NH; h++) {
        float acc = sp[S0_OFF + h];
#pragma unroll
        for (int i = 0; i < 3; i++) {
            float t = sp[LIN_OFF + h * 3 + i];
#pragma unroll
            for (int j = 0; j < 3; j++)
                t = fmaf(sp[A_OFF + h * 9 + i * 3 + j], r[j], t);
            acc = fmaf(r[i], t, acc);
        }
        s[h] = acc;
        mx = fmaxf(mx, acc);
    }
    float a[NH], den = 0.f;
#pragma unroll
    for (int h = 0; h < NH; h++) { a[h] = __expf(s[h] - mx); den += a[h]; }
    float dinv = 1.0f / den;

    float* base = &g_seg[(size_t)col * U16];
#pragma unroll
    for (int h = 0; h < NH; h++) {
        float ah = a[h] * dinv;
        red_add_v4(base + h * 4, make_float4(ah * r[0], ah * r[1], ah * r[2], ah));
    }
}

__global__ void __launch_bounds__(256) edge_kernel(const int* __restrict__ eraw) {
    __shared__ float sp[SCORE_SZ];
    if (threadIdx.x < SCORE_SZ) sp[threadIdx.x] = g_fold[threadIdx.x];
    __syncthreads();

    int e0 = (blockIdx.x * blockDim.x + threadIdx.x) * 2;
    if (e0 >= NE) return;

    int row0, col0, row1, col1;
    if (g_is64) {
        const longlong2* pr = reinterpret_cast<const longlong2*>(eraw);
        longlong2 rw = __ldg(&pr[e0 >> 1]);            // rows e0, e0+1
        longlong2 cl = __ldg(&pr[(NE + e0) >> 1]);     // cols e0, e0+1
        row0 = (int)rw.x; row1 = (int)rw.y;
        col0 = (int)cl.x; col1 = (int)cl.y;
    } else {
        const int2* pi = reinterpret_cast<const int2*>(eraw);
        int2 rw = __ldg(&pi[e0 >> 1]);
        int2 cl = __ldg(&pi[(NE + e0) >> 1]);
        row0 = rw.x; row1 = rw.y;
        col0 = cl.x; col1 = cl.y;
    }

    float4 pr0 = g_pos4[row0];
    float4 pc0 = g_pos4[col0];
    float4 pr1 = g_pos4[row1];
    float4 pc1 = g_pos4[col1];

    edge_compute(sp, col0, pr0, pc0);
    edge_compute(sp, col1, pr1, pc1);
}

// ---------------- kernel 3: per-node u@B + LN + SiLU (quad-sub, 2 nodes/thread) ----------------
__global__ void __launch_bounds__(256) node_kernel(float* __restrict__ out) {
    __shared__ __align__(16) float sB[U16 * HD];   // 512 floats
    __shared__ __align__(16) float sEpi[3 * HD];   // bout | gamma | beta

    for (int i = threadIdx.x; i < U16 * HD; i += 256) sB[i] = g_fold[B_OFF + i];
    for (int i = threadIdx.x; i < 3 * HD; i += 256)  sEpi[i] = g_fold[BOUT_OFF + i];
    __syncthreads();

    int gt   = blockIdx.x * blockDim.x + threadIdx.x;
    int pair = gt >> 2;
    int sub  = gt & 3;
    int n0   = pair * 2;          // NN is even -> n0, n0+1 both valid when n0 < NN
    bool valid = (n0 < NN);
    unsigned mask = 0xffffffffu;

    float s0[U16], s1[U16];
    if (valid) {
        const float4* p0 = reinterpret_cast<const float4*>(&g_seg[(size_t)n0 * U16]);
        const float4* p1 = reinterpret_cast<const float4*>(&g_seg[(size_t)(n0 + 1) * U16]);
#pragma unroll
        for (int k = 0; k < 4; k++) {
            float4 v = p0[k];
            s0[k*4+0]=v.x; s0[k*4+1]=v.y; s0[k*4+2]=v.z; s0[k*4+3]=v.w;
        }
#pragma unroll
        for (int k = 0; k < 4; k++) {
            float4 v = p1[k];
            s1[k*4+0]=v.x; s1[k*4+1]=v.y; s1[k*4+2]=v.z; s1[k*4+3]=v.w;
        }
    } else {
#pragma unroll
        for (int k = 0; k < U16; k++) { s0[k] = 0.f; s1[k] = 0.f; }
    }

    // all quad reads done -> safe to re-zero our slice for the next launch
    __syncwarp(mask);
    if (valid) {
        float4 z = make_float4(0.f, 0.f, 0.f, 0.f);
        reinterpret_cast<float4*>(&g_seg[(size_t)n0 * U16])[sub] = z;
        reinterpret_cast<float4*>(&g_seg[(size_t)(n0 + 1) * U16])[sub] = z;
    }

    float rinv0 = 1.0f / fmaxf(s0[3] + s0[7] + s0[11] + s0[15], 1.0f);
    float rinv1 = 1.0f / fmaxf(s1[3] + s1[7] + s1[11] + s1[15], 1.0f);

    const int o0 = sub * 8;
    float y0[8], y1[8];
#pragma unroll
    for (int c = 0; c < 8; c++) { y0[c] = 0.f; y1[c] = 0.f; }
#pragma unroll
    for (int j = 0; j < U16; j++) {
        const float4* brow = reinterpret_cast<const float4*>(&sB[j * HD + o0]);
        float4 b0 = brow[0], b1 = brow[1];
        float a0 = s0[j], a1 = s1[j];
        y0[0]=fmaf(a0,b0.x,y0[0]); y0[1]=fmaf(a0,b0.y,y0[1]);
        y0[2]=fmaf(a0,b0.z,y0[2]); y0[3]=fmaf(a0,b0.w,y0[3]);
        y0[4]=fmaf(a0,b1.x,y0[4]); y0[5]=fmaf(a0,b1.y,y0[5]);
        y0[6]=fmaf(a0,b1.z,y0[6]); y0[7]=fmaf(a0,b1.w,y0[7]);
        y1[0]=fmaf(a1,b0.x,y1[0]); y1[1]=fmaf(a1,b0.y,y1[1]);
        y1[2]=fmaf(a1,b0.z,y1[2]); y1[3]=fmaf(a1,b0.w,y1[3]);
        y1[4]=fmaf(a1,b1.x,y1[4]); y1[5]=fmaf(a1,b1.y,y1[5]);
        y1[6]=fmaf(a1,b1.z,y1[6]); y1[7]=fmaf(a1,b1.w,y1[7]);
    }

    float sum0 = 0.f, sum1 = 0.f;
#pragma unroll
    for (int c = 0; c < 8; c++) {
        y0[c] = fmaf(y0[c], rinv0, sEpi[o0 + c]);
        y1[c] = fmaf(y1[c], rinv1, sEpi[o0 + c]);
        sum0 += y0[c]; sum1 += y1[c];
    }
    sum0 += __shfl_xor_sync(mask, sum0, 1);
    sum0 += __shfl_xor_sync(mask, sum0, 2);
    sum1 += __shfl_xor_sync(mask, sum1, 1);
    sum1 += __shfl_xor_sync(mask, sum1, 2);
    float mu0 = sum0 * (1.0f / 32.0f);
    float mu1 = sum1 * (1.0f / 32.0f);

    float sq0 = 0.f, sq1 = 0.f;
#pragma unroll
    for (int c = 0; c < 8; c++) {
        float d0 = y0[c] - mu0; sq0 = fmaf(d0, d0, sq0);
        float d1 = y1[c] - mu1; sq1 = fmaf(d1, d1, sq1);
    }
    sq0 += __shfl_xor_sync(mask, sq0, 1);
    sq0 += __shfl_xor_sync(mask, sq0, 2);
    sq1 += __shfl_xor_sync(mask, sq1, 1);
    sq1 += __shfl_xor_sync(mask, sq1, 2);
    float sf0 = rsqrtf(sq0 * (1.0f / 32.0f) + 1e-5f);
    float sf1 = rsqrtf(sq1 * (1.0f / 32.0f) + 1e-5f);

    if (!valid) return;

    float4* op0 = reinterpret_cast<float4*>(&out[(size_t)n0 * HD + o0]);
    float4* op1 = reinterpret_cast<float4*>(&out[(size_t)(n0 + 1) * HD + o0]);
#pragma unroll
    for (int k = 0; k < 2; k++) {
        float4 v0, v1;
        float* vp0 = &v0.x;
        float* vp1 = &v1.x;
#pragma unroll
        for (int c = 0; c < 4; c++) {
            int o = o0 + k * 4 + c;
            float g = sEpi[HD + o], bt = sEpi[2 * HD + o];
            float x0 = (y0[k*4+c] - mu0) * sf0 * g + bt;
            float x1 = (y1[k*4+c] - mu1) * sf1 * g + bt;
            vp0[c] = x0 / (1.0f + __expf(-x0));
            vp1[c] = x1 / (1.0f + __expf(-x1));
        }
        op0[k] = v0;
        op1[k] = v1;
    }
}

// ---------------- launch ----------------
extern "C" void kernel_launch(void* const* d_in, const int* in_sizes, int n_in,
                              void* d_out, int out_size) {
    const float* pos   = (const float*)d_in[0];
    const int*   edge  = (const int*)d_in[1];
    const float* Wq    = (const float*)d_in[2];
    const float* bq    = (const float*)d_in[3];
    const float* Wk    = (const float*)d_in[4];
    const float* bk    = (const float*)d_in[5];
    const float* Wv    = (const float*)d_in[6];
    const float* bv    = (const float*)d_in[7];
    const float* Wout  = (const float*)d_in[8];
    const float* bout  = (const float*)d_in[9];
    const float* gamma = (const float*)d_in[10];
    const float* beta  = (const float*)d_in[11];
    float* out = (float*)d_out;

    pack_setup_kernel<<<392, 256>>>(pos, edge, Wq, bq, Wk, bk, Wv, bv, Wout, bout, gamma, beta);
    edge_kernel<<<(NE / 2 + 255) / 256, 256>>>(edge);
    node_kernel<<<(NN / 2 * 4 + 255) / 256, 256>>>(out);
}

// round 6
// speedup vs baseline: 2.1793x; 1.0652x over previous
#include <cuda_runtime.h>

#define NN 100000   // nodes
#define NE 500000   // edges
#define NH 4        // heads
#define HD 32       // output width
#define PROJ 128
#define U16 16      // folded edge-feature width

// folded-parameter layout inside g_fold (floats)
#define A_OFF     0            // 4*3*3 = 36  quadratic form (pre-scaled 1/sqrt(32))
#define LIN_OFF   36           // 4*3  = 12
#define S0_OFF    48           // 4
#define SCORE_SZ  52
#define B_OFF     52           // 16*32 = 512
#define BOUT_OFF  564          // 32
#define GAMMA_OFF 596          // 32
#define BETA_OFF  628          // 32
#define FOLD_SZ   660

// ---------------- device scratch (no allocations allowed) ----------------
// g_seg starts zeroed (static init) and is re-zeroed by node_kernel every
// launch after it consumes the values, so each edge_kernel sees zeros.
__device__ __align__(16) float g_seg[NN * U16];
__device__ __align__(16) float4 g_pos4[NN];      // padded positions for 1-LDG gathers
__device__ __align__(16) float g_fold[FOLD_SZ];  // folded params
__device__ int   g_is64;                         // edge_index dtype flag

// ---------------- kernel 1: pack positions + MLP-friendly weight fold ----------------
__global__ void __launch_bounds__(256) pack_setup_kernel(
        const float* __restrict__ pos,
        const int* __restrict__ eraw,
        const float* __restrict__ Wq, const float* __restrict__ bq,
        const float* __restrict__ Wk, const float* __restrict__ bk,
        const float* __restrict__ Wv, const float* __restrict__ bv,
        const float* __restrict__ Wout, const float* __restrict__ bout,
        const float* __restrict__ gamma, const float* __restrict__ beta) {
    int i = blockIdx.x * blockDim.x + threadIdx.x;
    int stride = gridDim.x * blockDim.x;
    for (int j = i; j < NN; j += stride)
        g_pos4[j] = make_float4(__ldg(&pos[j * 3 + 0]),
                                __ldg(&pos[j * 3 + 1]),
                                __ldg(&pos[j * 3 + 2]), 0.f);

    const int t = threadIdx.x;
    const float inv = 0.17677669529663687f;  // 1/sqrt(32)

    if (blockIdx.x < 2) {
        // ---- B fold: one thread per output, lane = o (coalesced Wout rows) ----
        // B[(h*4+ii)][o] = sum_d Wv[ii, h*32+d] * Wout[h*32+d, o]   (ii < 3)
        // B[(h*4+3)][o]  = sum_d bv[h*32+d]     * Wout[h*32+d, o]
        int idx = blockIdx.x * 256 + t;           // 0..511
        int j = idx >> 5, o = idx & 31;
        int h = j >> 2, ii = j & 3;
        const float* wsrc = (ii < 3) ? &Wv[ii * PROJ + h * HD] : &bv[h * HD];
        const float* wo   = &Wout[(size_t)h * HD * HD + o];
        float a0 = 0.f, a1 = 0.f, a2 = 0.f, a3 = 0.f;
#pragma unroll
        for (int d = 0; d < HD; d += 4) {
            a0 = fmaf(__ldg(&wsrc[d + 0]), __ldg(&wo[(d + 0) * HD]), a0);
            a1 = fmaf(__ldg(&wsrc[d + 1]), __ldg(&wo[(d + 1) * HD]), a1);
            a2 = fmaf(__ldg(&wsrc[d + 2]), __ldg(&wo[(d + 2) * HD]), a2);
            a3 = fmaf(__ldg(&wsrc[d + 3]), __ldg(&wo[(d + 3) * HD]), a3);
        }
        g_fold[B_OFF + idx] = (a0 + a1) + (a2 + a3);
        return;
    }

    if (blockIdx.x != 2) return;

    // ---- score folds: one thread per output, unrolled (high MLP) ----
    if (t < NH * 9) {
        // A_h[i][j] = sum_d Wq[i, h*32+d] * Wk[j, h*32+d]   (scaled)
        int h = t / 9, ii = (t % 9) / 3, jj = t % 3;
        const float* wq = &Wq[ii * PROJ + h * HD];
        const float* wk = &Wk[jj * PROJ + h * HD];
        float a0 = 0.f, a1 = 0.f, a2 = 0.f, a3 = 0.f;
#pragma unroll
        for (int d = 0; d < HD; d += 4) {
            a0 = fmaf(__ldg(&wq[d + 0]), __ldg(&wk[d + 0]), a0);
            a1 = fmaf(__ldg(&wq[d + 1]), __ldg(&wk[d + 1]), a1);
            a2 = fmaf(__ldg(&wq[d + 2]), __ldg(&wk[d + 2]), a2);
            a3 = fmaf(__ldg(&wq[d + 3]), __ldg(&wk[d + 3]), a3);
        }
        g_fold[A_OFF + t] = ((a0 + a1) + (a2 + a3)) * inv;
    } else if (t < 48) {
        // lin_h[i] = sum_d (Wq[i,hd]*bk[hd] + Wk[i,hd]*bq[hd])   (scaled)
        int idx = t - 36;
        int h = idx / 3, ii = idx % 3;
        const float* wq = &Wq[ii * PROJ + h * HD];
        const float* wk = &Wk[ii * PROJ + h * HD];
        const float* bqv = &bq[h * HD];
        const float* bkv = &bk[h * HD];
        float a0 = 0.f, a1 = 0.f;
#pragma unroll
        for (int d = 0; d < HD; d += 2) {
            a0 = fmaf(__ldg(&wq[d]),     __ldg(&bkv[d]),
                 fmaf(__ldg(&wk[d]),     __ldg(&bqv[d]), a0));
            a1 = fmaf(__ldg(&wq[d + 1]), __ldg(&bkv[d + 1]),
                 fmaf(__ldg(&wk[d + 1]), __ldg(&bqv[d + 1]), a1));
        }
        g_fold[LIN_OFF + idx] = (a0 + a1) * inv;
    } else if (t < 52) {
        // s0_h = bq_h . bk_h  (scaled)
        int h = t - 48;
        const float* bqv = &bq[h * HD];
        const float* bkv = &bk[h * HD];
        float a0 = 0.f, a1 = 0.f;
#pragma unroll
        for (int d = 0; d < HD; d += 2) {
            a0 = fmaf(__ldg(&bqv[d]),     __ldg(&bkv[d]),     a0);
            a1 = fmaf(__ldg(&bqv[d + 1]), __ldg(&bkv[d + 1]), a1);
        }
        g_fold[S0_OFF + h] = (a0 + a1) * inv;
    } else if (t >= 64 && t < 160) {
        // epilogue params: bout | gamma | beta
        int idx = t - 64;
        const float* src = (idx < HD) ? &bout[idx]
                         : (idx < 2 * HD) ? &gamma[idx - HD]
                         : &beta[idx - 2 * HD];
        g_fold[BOUT_OFF + idx] = __ldg(src);
    } else if (t == 192) {
        // int64 edge_index: node ids < 1e5 -> every odd 32-bit word is 0.
        int acc = 0;
#pragma unroll
        for (int k = 0; k < 32; k++) acc |= __ldg(&eraw[2 * k + 1]);
        g_is64 = (acc == 0);
    }
}

// ---------------- kernel 2: per-edge scores + 16-wide scatter (2 edges/thread) ----------------
__device__ __forceinline__ void red_add_v4(float* p, float4 v) {
    asm volatile("red.global.add.v4.f32 [%0], {%1,%2,%3,%4};"
                 :: "l"(p), "f"(v.x), "f"(v.y), "f"(v.z), "f"(v.w)
                 : "memory");
}

__device__ __forceinline__ void edge_compute(const float* sp, int col, float4 pr, float4 pc) {
    float r[3] = { pr.x - pc.x, pr.y - pc.y, pr.z - pc.z };
    float s[NH];
    float mx = -1e30f;
#pragma unroll
    for (int h = 0; h < NH; h++) {
        float acc = sp[S0_OFF + h];
#pragma unroll
        for (int i = 0; i < 3; i++) {
            float t = sp[LIN_OFF + h * 3 + i];
#pragma unroll
            for (int j = 0; j < 3; j++)
                t = fmaf(sp[A_OFF + h * 9 + i * 3 + j], r[j], t);
            acc = fmaf(r[i], t, acc);
        }
        s[h] = acc;
        mx = fmaxf(mx, acc);
    }
    float a[NH], den = 0.f;
#pragma unroll
    for (int h = 0; h < NH; h++) { a[h] = __expf(s[h] - mx); den += a[h]; }
    float dinv = 1.0f / den;

    float* base = &g_seg[(size_t)col * U16];
#pragma unroll
    for (int h = 0; h < NH; h++) {
        float ah = a[h] * dinv;
        red_add_v4(base + h * 4, make_float4(ah * r[0], ah * r[1], ah * r[2], ah));
    }
}

__global__ void __launch_bounds__(256) edge_kernel(const int* __restrict__ eraw) {
    __shared__ float sp[SCORE_SZ];
    if (threadIdx.x < SCORE_SZ) sp[threadIdx.x] = g_fold[threadIdx.x];
    __syncthreads();

    int e0 = (blockIdx.x * blockDim.x + threadIdx.x) * 2;
    if (e0 >= NE) return;

    int row0, col0, row1, col1;
    if (g_is64) {
        const longlong2* pr = reinterpret_cast<const longlong2*>(eraw);
        longlong2 rw = __ldg(&pr[e0 >> 1]);            // rows e0, e0+1
        longlong2 cl = __ldg(&pr[(NE + e0) >> 1]);     // cols e0, e0+1
        row0 = (int)rw.x; row1 = (int)rw.y;
        col0 = (int)cl.x; col1 = (int)cl.y;
    } else {
        const int2* pi = reinterpret_cast<const int2*>(eraw);
        int2 rw = __ldg(&pi[e0 >> 1]);
        int2 cl = __ldg(&pi[(NE + e0) >> 1]);
        row0 = rw.x; row1 = rw.y;
        col0 = cl.x; col1 = cl.y;
    }

    float4 pr0 = g_pos4[row0];
    float4 pc0 = g_pos4[col0];
    float4 pr1 = g_pos4[row1];
    float4 pc1 = g_pos4[col1];

    edge_compute(sp, col0, pr0, pc0);
    edge_compute(sp, col1, pr1, pc1);
}

// ---------------- kernel 3: per-node u@B + LN + SiLU (quad-sub, 2 nodes/thread) ----------------
__global__ void __launch_bounds__(256) node_kernel(float* __restrict__ out) {
    __shared__ __align__(16) float sB[U16 * HD];   // 512 floats
    __shared__ __align__(16) float sEpi[3 * HD];   // bout | gamma | beta

    for (int i = threadIdx.x; i < U16 * HD; i += 256) sB[i] = g_fold[B_OFF + i];
    for (int i = threadIdx.x; i < 3 * HD; i += 256)  sEpi[i] = g_fold[BOUT_OFF + i];
    __syncthreads();

    int gt   = blockIdx.x * blockDim.x + threadIdx.x;
    int pair = gt >> 2;
    int sub  = gt & 3;
    int n0   = pair * 2;          // NN is even -> n0, n0+1 both valid when n0 < NN
    bool valid = (n0 < NN);
    unsigned mask = 0xffffffffu;

    float s0[U16], s1[U16];
    if (valid) {
        const float4* p0 = reinterpret_cast<const float4*>(&g_seg[(size_t)n0 * U16]);
        const float4* p1 = reinterpret_cast<const float4*>(&g_seg[(size_t)(n0 + 1) * U16]);
#pragma unroll
        for (int k = 0; k < 4; k++) {
            float4 v = p0[k];
            s0[k*4+0]=v.x; s0[k*4+1]=v.y; s0[k*4+2]=v.z; s0[k*4+3]=v.w;
        }
#pragma unroll
        for (int k = 0; k < 4; k++) {
            float4 v = p1[k];
            s1[k*4+0]=v.x; s1[k*4+1]=v.y; s1[k*4+2]=v.z; s1[k*4+3]=v.w;
        }
    } else {
#pragma unroll
        for (int k = 0; k < U16; k++) { s0[k] = 0.f; s1[k] = 0.f; }
    }

    // all quad reads done -> safe to re-zero our slice for the next launch
    __syncwarp(mask);
    if (valid) {
        float4 z = make_float4(0.f, 0.f, 0.f, 0.f);
        reinterpret_cast<float4*>(&g_seg[(size_t)n0 * U16])[sub] = z;
        reinterpret_cast<float4*>(&g_seg[(size_t)(n0 + 1) * U16])[sub] = z;
    }

    float rinv0 = 1.0f / fmaxf(s0[3] + s0[7] + s0[11] + s0[15], 1.0f);
    float rinv1 = 1.0f / fmaxf(s1[3] + s1[7] + s1[11] + s1[15], 1.0f);

    const int o0 = sub * 8;
    float y0[8], y1[8];
#pragma unroll
    for (int c = 0; c < 8; c++) { y0[c] = 0.f; y1[c] = 0.f; }
#pragma unroll
    for (int j = 0; j < U16; j++) {
        const float4* brow = reinterpret_cast<const float4*>(&sB[j * HD + o0]);
        float4 b0 = brow[0], b1 = brow[1];
        float a0 = s0[j], a1 = s1[j];
        y0[0]=fmaf(a0,b0.x,y0[0]); y0[1]=fmaf(a0,b0.y,y0[1]);
        y0[2]=fmaf(a0,b0.z,y0[2]); y0[3]=fmaf(a0,b0.w,y0[3]);
        y0[4]=fmaf(a0,b1.x,y0[4]); y0[5]=fmaf(a0,b1.y,y0[5]);
        y0[6]=fmaf(a0,b1.z,y0[6]); y0[7]=fmaf(a0,b1.w,y0[7]);
        y1[0]=fmaf(a1,b0.x,y1[0]); y1[1]=fmaf(a1,b0.y,y1[1]);
        y1[2]=fmaf(a1,b0.z,y1[2]); y1[3]=fmaf(a1,b0.w,y1[3]);
        y1[4]=fmaf(a1,b1.x,y1[4]); y1[5]=fmaf(a1,b1.y,y1[5]);
        y1[6]=fmaf(a1,b1.z,y1[6]); y1[7]=fmaf(a1,b1.w,y1[7]);
    }

    float sum0 = 0.f, sum1 = 0.f;
#pragma unroll
    for (int c = 0; c < 8; c++) {
        y0[c] = fmaf(y0[c], rinv0, sEpi[o0 + c]);
        y1[c] = fmaf(y1[c], rinv1, sEpi[o0 + c]);
        sum0 += y0[c]; sum1 += y1[c];
    }
    sum0 += __shfl_xor_sync(mask, sum0, 1);
    sum0 += __shfl_xor_sync(mask, sum0, 2);
    sum1 += __shfl_xor_sync(mask, sum1, 1);
    sum1 += __shfl_xor_sync(mask, sum1, 2);
    float mu0 = sum0 * (1.0f / 32.0f);
    float mu1 = sum1 * (1.0f / 32.0f);

    float sq0 = 0.f, sq1 = 0.f;
#pragma unroll
    for (int c = 0; c < 8; c++) {
        float d0 = y0[c] - mu0; sq0 = fmaf(d0, d0, sq0);
        float d1 = y1[c] - mu1; sq1 = fmaf(d1, d1, sq1);
    }
    sq0 += __shfl_xor_sync(mask, sq0, 1);
    sq0 += __shfl_xor_sync(mask, sq0, 2);
    sq1 += __shfl_xor_sync(mask, sq1, 1);
    sq1 += __shfl_xor_sync(mask, sq1, 2);
    float sf0 = rsqrtf(sq0 * (1.0f / 32.0f) + 1e-5f);
    float sf1 = rsqrtf(sq1 * (1.0f / 32.0f) + 1e-5f);

    if (!valid) return;

    float4* op0 = reinterpret_cast<float4*>(&out[(size_t)n0 * HD + o0]);
    float4* op1 = reinterpret_cast<float4*>(&out[(size_t)(n0 + 1) * HD + o0]);
#pragma unroll
    for (int k = 0; k < 2; k++) {
        float4 v0, v1;
        float* vp0 = &v0.x;
        float* vp1 = &v1.x;
#pragma unroll
        for (int c = 0; c < 4; c++) {
            int o = o0 + k * 4 + c;
            float g = sEpi[HD + o], bt = sEpi[2 * HD + o];
            float x0 = (y0[k*4+c] - mu0) * sf0 * g + bt;
            float x1 = (y1[k*4+c] - mu1) * sf1 * g + bt;
            vp0[c] = x0 / (1.0f + __expf(-x0));
            vp1[c] = x1 / (1.0f + __expf(-x1));
        }
        op0[k] = v0;
        op1[k] = v1;
    }
}

// ---------------- launch ----------------
extern "C" void kernel_launch(void* const* d_in, const int* in_sizes, int n_in,
                              void* d_out, int out_size) {
    const float* pos   = (const float*)d_in[0];
    const int*   edge  = (const int*)d_in[1];
    const float* Wq    = (const float*)d_in[2];
    const float* bq    = (const float*)d_in[3];
    const float* Wk    = (const float*)d_in[4];
    const float* bk    = (const float*)d_in[5];
    const float* Wv    = (const float*)d_in[6];
    const float* bv    = (const float*)d_in[7];
    const float* Wout  = (const float*)d_in[8];
    const float* bout  = (const float*)d_in[9];
    const float* gamma = (const float*)d_in[10];
    const float* beta  = (const float*)d_in[11];
    float* out = (float*)d_out;

    pack_setup_kernel<<<392, 256>>>(pos, edge, Wq, bq, Wk, bk, Wv, bv, Wout, bout, gamma, beta);
    edge_kernel<<<(NE / 2 + 255) / 256, 256>>>(edge);
    node_kernel<<<(NN / 2 * 4 + 255) / 256, 256>>>(out);
}